// round 2
// baseline (speedup 1.0000x reference)
#include <cuda_runtime.h>
#include <math.h>

#define BB   16384
#define NM   64
#define NDV  64
#define NDQA 128
#define NMV  4096

// ---------------- scratch (device globals; no allocs allowed) ----------------
__device__ float g_content0[BB * NDQA];          //  8 MB
__device__ float g_c0ez[BB * NDQA];              //  8 MB  [c0@We+be | c0@Wz+bz]
__device__ float g_mempre[(size_t)BB * NMV];     // 256 MB
__device__ float g_sig[BB * 192];                // 12 MB  [semv+bemv | szmv+bzmv | samv+bamv]
__device__ float g_zt[BB * NDV];                 //  4 MB
__device__ float g_erase[BB * NDV];              //  4 MB
__device__ float g_ztwza[BB * NDV];              //  4 MB  zt@Wza + bza
__device__ float g_ww[BB * NM];                  //  4 MB

__device__ __forceinline__ float sigmoidf_(float x) { return 1.0f / (1.0f + __expf(-x)); }

enum { M_C0 = 0, M_EZ = 1, M_GATE = 2, M_SIG = 3, M_ZA = 4 };

// ---------------- generic tiled fp32 GEMM with fused epilogues ----------------
// C[16384 x N] = A[16384 x KC] @ W[KC x N]  (all row-major), BM=128, BK=16, TM=8
template <int MODE, int BN, int TN, int KC, int LDA>
__global__ void __launch_bounds__(256) gemm_k(
    const float* __restrict__ Aarg,
    const float* __restrict__ W0, const float* __restrict__ W1, const float* __restrict__ W2,
    const float* __restrict__ b0, const float* __restrict__ b1, const float* __restrict__ b2,
    const float* __restrict__ X)
{
    constexpr int BM = 128, BK = 16, TM = 8;
    __shared__ float As[BK][BM];   // transposed A tile
    __shared__ float Bs[BK][BN];

    const float* A;
    if constexpr (MODE == M_C0)                        A = Aarg;        // memory_value
    else if constexpr (MODE == M_EZ || MODE == M_GATE) A = g_content0;
    else if constexpr (MODE == M_SIG)                  A = g_mempre;
    else                                               A = g_zt;

    const int tid  = threadIdx.x;
    const int trow = tid >> 4;   // 0..15
    const int tcol = tid & 15;   // 0..15
    const int m0 = blockIdx.x * BM;
    const int n0 = blockIdx.y * BN;

    float acc[TM][TN];
#pragma unroll
    for (int i = 0; i < TM; i++)
#pragma unroll
        for (int j = 0; j < TN; j++) acc[i][j] = 0.f;

    for (int kt = 0; kt < KC; kt += BK) {
        // ---- load A tile (BM x BK) transposed into smem ----
#pragma unroll
        for (int v0 = 0; v0 < 2; v0++) {
            int v  = tid + v0 * 256;        // 0..511 float4 slots
            int r  = v >> 2;                // row 0..127
            int c4 = (v & 3) * 4;           // col 0,4,8,12
            float4 t = *(const float4*)&A[(size_t)(m0 + r) * LDA + kt + c4];
            As[c4 + 0][r] = t.x; As[c4 + 1][r] = t.y;
            As[c4 + 2][r] = t.z; As[c4 + 3][r] = t.w;
        }
        // ---- load B tile (BK x BN) ----
        constexpr int BV = (BK * BN) / (4 * 256);
#pragma unroll
        for (int v0 = 0; v0 < BV; v0++) {
            int v  = tid + v0 * 256;
            int r  = v / (BN / 4);
            int c4 = (v % (BN / 4)) * 4;
            int kg = kt + r;
            int ng = n0 + c4;
            float4 t;
            if constexpr (MODE == M_SIG) {
                int w = ng >> 6, nc = ng & 63;
                const float* W = (w == 0) ? W0 : ((w == 1) ? W1 : W2);
                t = *(const float4*)&W[(size_t)kg * 64 + nc];
            } else if constexpr (MODE == M_EZ) {
                int w = ng >> 6, nc = ng & 63;
                const float* W = (w == 0) ? W0 : W1;
                t = *(const float4*)&W[(size_t)kg * 64 + nc];
            } else if constexpr (MODE == M_GATE) {
                t = *(const float4*)&W0[(size_t)kg * 4096 + ng];
            } else if constexpr (MODE == M_C0) {
                t = *(const float4*)&W0[(size_t)kg * 128 + ng];
            } else { // M_ZA
                t = *(const float4*)&W0[(size_t)kg * 64 + ng];
            }
            *(float4*)&Bs[r][c4] = t;
        }
        __syncthreads();

#pragma unroll
        for (int kk = 0; kk < BK; kk++) {
            float a[TM], bv[TN];
#pragma unroll
            for (int i = 0; i < TM; i += 4) {
                float4 t = *(const float4*)&As[kk][trow * TM + i];
                a[i] = t.x; a[i + 1] = t.y; a[i + 2] = t.z; a[i + 3] = t.w;
            }
#pragma unroll
            for (int j = 0; j < TN; j += 4) {
                float4 t = *(const float4*)&Bs[kk][tcol * TN + j];
                bv[j] = t.x; bv[j + 1] = t.y; bv[j + 2] = t.z; bv[j + 3] = t.w;
            }
#pragma unroll
            for (int i = 0; i < TM; i++)
#pragma unroll
                for (int j = 0; j < TN; j++)
                    acc[i][j] = fmaf(a[i], bv[j], acc[i][j]);
        }
        __syncthreads();
    }

    // ---- epilogue ----
#pragma unroll
    for (int i = 0; i < TM; i++) {
        int rg = m0 + trow * TM + i;
#pragma unroll
        for (int j = 0; j < TN; j += 4) {
            int ng = n0 + tcol * TN + j;
            float4 o;
            if constexpr (MODE == M_C0) {
                float4 bq = *(const float4*)&b0[ng];
                float4 xq = *(const float4*)&X[(size_t)rg * 128 + ng];
                o.x = xq.x * sigmoidf_(acc[i][j + 0] + bq.x);
                o.y = xq.y * sigmoidf_(acc[i][j + 1] + bq.y);
                o.z = xq.z * sigmoidf_(acc[i][j + 2] + bq.z);
                o.w = xq.w * sigmoidf_(acc[i][j + 3] + bq.w);
                *(float4*)&g_content0[(size_t)rg * 128 + ng] = o;
            } else if constexpr (MODE == M_EZ) {
                const float* bp = (ng < 64) ? (b0 + ng) : (b1 + (ng - 64));
                float4 bq = *(const float4*)bp;
                o.x = acc[i][j + 0] + bq.x; o.y = acc[i][j + 1] + bq.y;
                o.z = acc[i][j + 2] + bq.z; o.w = acc[i][j + 3] + bq.w;
                *(float4*)&g_c0ez[(size_t)rg * 128 + ng] = o;
            } else if constexpr (MODE == M_GATE) {
                float4 bq = *(const float4*)&b0[ng];
                float4 xq = *(const float4*)&X[(size_t)rg * 4096 + ng];
                o.x = xq.x * sigmoidf_(acc[i][j + 0] + bq.x);
                o.y = xq.y * sigmoidf_(acc[i][j + 1] + bq.y);
                o.z = xq.z * sigmoidf_(acc[i][j + 2] + bq.z);
                o.w = xq.w * sigmoidf_(acc[i][j + 3] + bq.w);
                *(float4*)&g_mempre[(size_t)rg * 4096 + ng] = o;
            } else if constexpr (MODE == M_SIG) {
                int w = ng >> 6, nc = ng & 63;
                const float* bp = ((w == 0) ? b0 : (w == 1) ? b1 : b2) + nc;
                float4 bq = *(const float4*)bp;
                o.x = acc[i][j + 0] + bq.x; o.y = acc[i][j + 1] + bq.y;
                o.z = acc[i][j + 2] + bq.z; o.w = acc[i][j + 3] + bq.w;
                *(float4*)&g_sig[(size_t)rg * 192 + ng] = o;
            } else { // M_ZA
                float4 bq = *(const float4*)&b0[ng];
                o.x = acc[i][j + 0] + bq.x; o.y = acc[i][j + 1] + bq.y;
                o.z = acc[i][j + 2] + bq.z; o.w = acc[i][j + 3] + bq.w;
                *(float4*)&g_ztwza[(size_t)rg * 64 + ng] = o;
            }
        }
    }
}

// ---------------- write_weight: softmax(control_key @ memory_key^T) ----------------
__global__ void __launch_bounds__(256) ww_k(const float* __restrict__ ck,
                                            const float* __restrict__ mk)
{
    int g = threadIdx.x >> 6;   // 4 rows per block
    int t = threadIdx.x & 63;
    int b = blockIdx.x * 4 + g;
    __shared__ float sck[4][64];
    __shared__ float pmax[4][2];
    __shared__ float psum[4][2];

    sck[g][t] = ck[b * 64 + t];
    __syncthreads();
    float dot = 0.f;
#pragma unroll 8
    for (int k = 0; k < 64; k++) dot = fmaf(sck[g][k], mk[t * 64 + k], dot);

    float mx = dot;
#pragma unroll
    for (int o = 16; o > 0; o >>= 1) mx = fmaxf(mx, __shfl_xor_sync(0xffffffffu, mx, o));
    int wl = t >> 5;
    if ((t & 31) == 0) pmax[g][wl] = mx;
    __syncthreads();
    mx = fmaxf(pmax[g][0], pmax[g][1]);

    float e = __expf(dot - mx);
    float s = e;
#pragma unroll
    for (int o = 16; o > 0; o >>= 1) s += __shfl_xor_sync(0xffffffffu, s, o);
    if ((t & 31) == 0) psum[g][wl] = s;
    __syncthreads();
    s = psum[g][0] + psum[g][1];

    g_ww[b * 64 + t] = e / s;
}

// ---------------- zt + erase (elementwise over B x 64) ----------------
__global__ void __launch_bounds__(256) zt_erase_k()
{
    int i = blockIdx.x * 256 + threadIdx.x;
    int b = i >> 6, j = i & 63;
    float cwe  = g_c0ez[b * 128 + j];         // c0@We + be
    float cwz  = g_c0ez[b * 128 + 64 + j];    // c0@Wz + bz
    float semv = g_sig[b * 192 + j];          // mempre@Wemv + bemv
    float szmv = g_sig[b * 192 + 64 + j];     // mempre@Wzmv + bzmv
    g_zt[i]    = sigmoidf_(cwz + szmv);
    g_erase[i] = sigmoidf_(sigmoidf_(cwe) + sigmoidf_(semv));
}

// ---------------- final: out = mempre*(1 - w*erase) + w*add ----------------
__global__ void __launch_bounds__(256) final_k(float* __restrict__ out)
{
    int b = blockIdx.x;
    int t = threadIdx.x;
    __shared__ float sww[64], ser[64], sadd[64];
    if (t < 64) {
        sww[t] = g_ww[b * 64 + t];
        ser[t] = g_erase[b * 64 + t];
        sadd[t] = tanhf(tanhf(g_ztwza[b * 64 + t]) + tanhf(g_sig[b * 192 + 128 + t]));
    }
    __syncthreads();
    const float4* mp = (const float4*)&g_mempre[(size_t)b * 4096];
    float4* op = (float4*)(out + (size_t)b * 4096);
#pragma unroll
    for (int it = 0; it < 4; it++) {
        int v  = t + it * 256;        // float4 index within row, 0..1023
        int m  = v >> 4;              // memory slot
        int dv = (v & 15) << 2;       // value offset
        float w = sww[m];
        float4 x = mp[v];
        float4 r;
        r.x = x.x * (1.f - w * ser[dv + 0]) + w * sadd[dv + 0];
        r.y = x.y * (1.f - w * ser[dv + 1]) + w * sadd[dv + 1];
        r.z = x.z * (1.f - w * ser[dv + 2]) + w * sadd[dv + 2];
        r.w = x.w * (1.f - w * ser[dv + 3]) + w * sadd[dv + 3];
        op[v] = r;
    }
}

// ---------------- launch ----------------
extern "C" void kernel_launch(void* const* d_in, const int* in_sizes, int n_in,
                              void* d_out, int out_size)
{
    const float* control_key  = (const float*)d_in[0];
    const float* control_qa   = (const float*)d_in[1];
    const float* memory_key   = (const float*)d_in[2];
    const float* memory_value = (const float*)d_in[3];
    const float* We   = (const float*)d_in[4];
    const float* be   = (const float*)d_in[5];
    const float* Wemv = (const float*)d_in[6];
    const float* bemv = (const float*)d_in[7];
    const float* Wza  = (const float*)d_in[8];
    const float* bza  = (const float*)d_in[9];
    const float* Wamv = (const float*)d_in[10];
    const float* bamv = (const float*)d_in[11];
    const float* Wc0  = (const float*)d_in[12];
    const float* bc0  = (const float*)d_in[13];
    const float* Wm1  = (const float*)d_in[14];
    const float* bm1  = (const float*)d_in[15];
    const float* Wz   = (const float*)d_in[16];
    const float* bz   = (const float*)d_in[17];
    const float* Wzmv = (const float*)d_in[18];
    const float* bzmv = (const float*)d_in[19];
    float* out = (float*)d_out;

    // write weights (independent)
    ww_k<<<BB / 4, 256>>>(control_key, memory_key);

    // content0 = qa * sigmoid(memory_value @ Wc0 + bc0)        [B x 128]
    gemm_k<M_C0, 128, 8, 4096, 4096><<<dim3(BB / 128, 1), 256>>>(
        memory_value, Wc0, nullptr, nullptr, bc0, nullptr, nullptr, control_qa);

    // c0ez = [c0@We + be | c0@Wz + bz]                          [B x 128]
    gemm_k<M_EZ, 128, 8, 128, 128><<<dim3(BB / 128, 1), 256>>>(
        nullptr, We, Wz, nullptr, be, bz, nullptr, nullptr);

    // mempre = memory_value * sigmoid(c0 @ Wm1 + bm1)           [B x 4096]
    gemm_k<M_GATE, 128, 8, 128, 128><<<dim3(BB / 128, 32), 256>>>(
        nullptr, Wm1, nullptr, nullptr, bm1, nullptr, nullptr, memory_value);

    // sig = mempre @ [Wemv|Wzmv|Wamv] + biases                  [B x 192]
    gemm_k<M_SIG, 192, 12, 4096, 4096><<<dim3(BB / 128, 1), 256>>>(
        nullptr, Wemv, Wzmv, Wamv, bemv, bzmv, bamv, nullptr);

    // zt, erase                                                  [B x 64]
    zt_erase_k<<<BB * 64 / 256, 256>>>();

    // ztwza = zt @ Wza + bza                                     [B x 64]
    gemm_k<M_ZA, 64, 4, 64, 64><<<dim3(BB / 128, 1), 256>>>(
        nullptr, Wza, nullptr, nullptr, bza, nullptr, nullptr, nullptr);

    // final elementwise
    final_k<<<BB, 256>>>(out);
}

// round 4
// speedup vs baseline: 1.5270x; 1.5270x over previous
#include <cuda_runtime.h>
#include <math.h>
#include <stdint.h>

#define BB   16384

// ---------------- scratch (device globals; no allocs allowed) ----------------
__device__ float g_content0[BB * 128];
__device__ float g_c0ez[BB * 128];
__device__ float g_mempre[(size_t)BB * 4096];
__device__ float g_sig[BB * 192];
__device__ float g_zt[BB * 64];
__device__ float g_erase[BB * 64];
__device__ float g_ztwza[BB * 64];
__device__ float g_ww[BB * 64];

__device__ __forceinline__ float sigmoidf_(float x) { return 1.0f / (1.0f + __expf(-x)); }

__device__ __forceinline__ uint32_t smem_u32(const void* p) {
    uint32_t a;
    asm("{ .reg .u64 t; cvta.to.shared.u64 t, %1; cvt.u32.u64 %0, t; }" : "=r"(a) : "l"(p));
    return a;
}
__device__ __forceinline__ uint32_t tf32r(float x) {
    uint32_t u; asm("cvt.rna.tf32.f32 %0, %1;" : "=r"(u) : "f"(x)); return u;
}
__device__ __forceinline__ void ldsm4(uint32_t* d, uint32_t addr) {
    asm volatile("ldmatrix.sync.aligned.m8n8.x4.shared.b16 {%0,%1,%2,%3}, [%4];"
        : "=r"(d[0]), "=r"(d[1]), "=r"(d[2]), "=r"(d[3]) : "r"(addr));
}
__device__ __forceinline__ void mma8(float* c, const uint32_t* a, uint32_t b0, uint32_t b1) {
    asm volatile("mma.sync.aligned.m16n8k8.row.col.f32.tf32.tf32.f32 "
        "{%0,%1,%2,%3}, {%4,%5,%6,%7}, {%8,%9}, {%0,%1,%2,%3};"
        : "+f"(c[0]), "+f"(c[1]), "+f"(c[2]), "+f"(c[3])
        : "r"(a[0]), "r"(a[1]), "r"(a[2]), "r"(a[3]), "r"(b0), "r"(b1));
}

// ====================== tf32 mma.sync GEMM with fused epilogues ======================
// C[16384 x N] = A[16384 x KC] @ W[KC x N]; BM=128, BK=32; 8 warps (2 M x 4 N).
enum { MM_C0 = 0, MM_GATE = 1, MM_SIG = 2 };

template <int MODE, int NB, int KC, int LDA>
__global__ void __launch_bounds__(256) mma_k(
    const float* __restrict__ Aarg,
    const float* __restrict__ W0, const float* __restrict__ W1, const float* __restrict__ W2,
    const float* __restrict__ b0, const float* __restrict__ b1, const float* __restrict__ b2,
    const float* __restrict__ X)
{
    constexpr int BK   = 32;
    constexpr int NCH  = KC / BK;
    constexpr int ABUF = 128 * BK * 4;          // 16 KB
    constexpr int BBUF = NB * BK * 4;
    constexpr int NT   = NB / 32;               // n-tiles (of 8) per warp
    constexpr int PAIRS = NT / 2;
    constexpr int GB   = NB / 32;               // B ldg tasks per thread
    constexpr int WN   = NB / 4;                // warp-column width
    constexpr int WNP  = WN + 4;                // padded stage stride (16B aligned)

    extern __shared__ char smem[];
    const int tid  = threadIdx.x;
    const int lane = tid & 31;
    const int wid  = tid >> 5;
    const int wm   = wid & 1;
    const int wn   = wid >> 1;
    const int m0   = blockIdx.x * 128;
    const int n0   = blockIdx.y * NB;

    const float* A = (MODE == MM_C0) ? Aarg : (MODE == MM_GATE) ? g_content0 : g_mempre;

    uint32_t sA = smem_u32(smem);
    uint32_t sB = sA + 2 * ABUF;

    float4 ar[4];
    float  br[GB][4];

    auto ldg = [&](int c) {
        const int kt = c * BK;
#pragma unroll
        for (int t = 0; t < 4; t++) {           // A: 128 rows x 32 k, float4 per task
            int v = tid + t * 256;
            int kq = v & 7, r = v >> 3;
            ar[t] = *(const float4*)&A[(size_t)(m0 + r) * LDA + kt + kq * 4];
        }
#pragma unroll
        for (int t = 0; t < GB; t++) {          // B: gather 4 k-values per n (coalesced in n)
            int v = tid + t * 256;
            int kq = v / NB, n = v - kq * NB;
#pragma unroll
            for (int j = 0; j < 4; j++) {
                int k = kt + kq * 4 + j;
                if constexpr (MODE == MM_SIG) {
                    int seg = n >> 6;
                    const float* W = (seg == 0) ? W0 : (seg == 1) ? W1 : W2;
                    br[t][j] = W[(size_t)k * 64 + (n & 63)];
                } else if constexpr (MODE == MM_GATE) {
                    br[t][j] = W0[(size_t)k * 4096 + n0 + n];
                } else {
                    br[t][j] = W0[(size_t)k * 128 + n];
                }
            }
        }
    };
    auto sts = [&](int p) {
        char* ab = smem + p * ABUF;
        char* bb = smem + 2 * ABUF + p * BBUF;
#pragma unroll
        for (int t = 0; t < 4; t++) {
            int v = tid + t * 256;
            int kq = v & 7, r = v >> 3;
            uint4 u;
            u.x = tf32r(ar[t].x); u.y = tf32r(ar[t].y);
            u.z = tf32r(ar[t].z); u.w = tf32r(ar[t].w);
            *(uint4*)(ab + (kq * 128 + r) * 16) = u;
        }
#pragma unroll
        for (int t = 0; t < GB; t++) {
            int v = tid + t * 256;
            int kq = v / NB, n = v - kq * NB;
            uint4 u;
            u.x = tf32r(br[t][0]); u.y = tf32r(br[t][1]);
            u.z = tf32r(br[t][2]); u.w = tf32r(br[t][3]);
            *(uint4*)(bb + (kq * NB + n) * 16) = u;
        }
    };

    // per-thread ldmatrix fragment offsets (16B-chunk layout: chunk(kb,row) at (kb*ROWS+row)*16)
    uint32_t aoff[4], boff[PAIRS];
#pragma unroll
    for (int mt = 0; mt < 4; mt++)
        aoff[mt] = (uint32_t)((((lane >> 4) * 128) + wm * 64 + mt * 16 + (lane & 15)) * 16);
#pragma unroll
    for (int pr = 0; pr < PAIRS; pr++)
        boff[pr] = (uint32_t)(((((lane >> 3) & 1) * NB) + wn * WN + pr * 16 +
                               (lane & 7) + ((lane >> 4) << 3)) * 16);

    float acc[4][NT][4];
#pragma unroll
    for (int mt = 0; mt < 4; mt++)
#pragma unroll
        for (int nt = 0; nt < NT; nt++)
#pragma unroll
            for (int j = 0; j < 4; j++) acc[mt][nt][j] = 0.f;

    auto compute = [&](int p) {
        uint32_t bufA = sA + p * ABUF;
        uint32_t bufB = sB + p * BBUF;
#pragma unroll
        for (int s = 0; s < 4; s++) {           // 4 k8-steps per BK=32 chunk
            uint32_t a[4][4];
#pragma unroll
            for (int mt = 0; mt < 4; mt++)
                ldsm4(a[mt], bufA + aoff[mt] + s * (2 * 128 * 16));
#pragma unroll
            for (int pr = 0; pr < PAIRS; pr++) {
                uint32_t b[4];
                ldsm4(b, bufB + boff[pr] + s * (2 * NB * 16));
#pragma unroll
                for (int mt = 0; mt < 4; mt++) {
                    mma8(acc[mt][2 * pr],     a[mt], b[0], b[1]);
                    mma8(acc[mt][2 * pr + 1], a[mt], b[2], b[3]);
                }
            }
        }
    };

    // ---- software-pipelined mainloop ----
    ldg(0); sts(0); __syncthreads();
#pragma unroll 1
    for (int c = 0; c < NCH; c++) {
        if (c + 1 < NCH) ldg(c + 1);
        compute(c & 1);
        if (c + 1 < NCH) { sts((c + 1) & 1); __syncthreads(); }
    }

    // ---- epilogue: fragments -> padded smem stage -> coalesced global ----
    __syncthreads();
    float* stage = (float*)smem;
#pragma unroll 1
    for (int g = 0; g < 4; g++) {
        if (wn == g) {
#pragma unroll
            for (int mt = 0; mt < 4; mt++)
#pragma unroll
                for (int nt = 0; nt < NT; nt++) {
                    int row = wm * 64 + mt * 16 + (lane >> 2);
                    int col = nt * 8 + 2 * (lane & 3);
                    *(float2*)&stage[row * WNP + col] =
                        make_float2(acc[mt][nt][0], acc[mt][nt][1]);
                    *(float2*)&stage[(row + 8) * WNP + col] =
                        make_float2(acc[mt][nt][2], acc[mt][nt][3]);
                }
        }
        __syncthreads();
        constexpr int ITER = 128 * WN / 4 / 256;
#pragma unroll
        for (int t = 0; t < ITER; t++) {
            int v = tid + t * 256;
            int row = v / (WN / 4);
            int c4  = (v - row * (WN / 4)) * 4;
            size_t rg = (size_t)(m0 + row);
            float4 d = *(float4*)&stage[row * WNP + c4];
            float dv[4] = {d.x, d.y, d.z, d.w};
            float o[4];
#pragma unroll
            for (int j = 0; j < 4; j++) {
                int n = g * WN + c4 + j;
                if constexpr (MODE == MM_C0) {
                    o[j] = X[rg * 128 + n] * sigmoidf_(dv[j] + b0[n]);
                } else if constexpr (MODE == MM_GATE) {
                    int ng = n0 + n;
                    o[j] = X[rg * 4096 + ng] * sigmoidf_(dv[j] + b0[ng]);
                } else {
                    int seg = n >> 6;
                    const float* bp = (seg == 0) ? b0 : (seg == 1) ? b1 : b2;
                    o[j] = dv[j] + bp[n & 63];
                }
            }
            float4 ov = make_float4(o[0], o[1], o[2], o[3]);
            if constexpr (MODE == MM_C0)
                *(float4*)&g_content0[rg * 128 + g * WN + c4] = ov;
            else if constexpr (MODE == MM_GATE)
                *(float4*)&g_mempre[rg * 4096 + n0 + g * WN + c4] = ov;
            else
                *(float4*)&g_sig[rg * 192 + g * WN + c4] = ov;
        }
        __syncthreads();
    }
}

// ====================== small SIMT GEMM (EZ / ZA) ======================
enum { M_EZ = 1, M_ZA = 4 };

template <int MODE, int BN, int TN, int KC, int LDA>
__global__ void __launch_bounds__(256) gemm_k(
    const float* __restrict__ W0, const float* __restrict__ W1,
    const float* __restrict__ b0, const float* __restrict__ b1)
{
    constexpr int BM = 128, BK = 16, TM = 8;
    __shared__ float As[BK][BM];
    __shared__ float Bs[BK][BN];

    const float* A = (MODE == M_EZ) ? g_content0 : g_zt;

    const int tid  = threadIdx.x;
    const int trow = tid >> 4;
    const int tcol = tid & 15;
    const int m0 = blockIdx.x * BM;

    float acc[TM][TN];
#pragma unroll
    for (int i = 0; i < TM; i++)
#pragma unroll
        for (int j = 0; j < TN; j++) acc[i][j] = 0.f;

    for (int kt = 0; kt < KC; kt += BK) {
#pragma unroll
        for (int v0 = 0; v0 < 2; v0++) {
            int v  = tid + v0 * 256;
            int r  = v >> 2;
            int c4 = (v & 3) * 4;
            float4 t = *(const float4*)&A[(size_t)(m0 + r) * LDA + kt + c4];
            As[c4 + 0][r] = t.x; As[c4 + 1][r] = t.y;
            As[c4 + 2][r] = t.z; As[c4 + 3][r] = t.w;
        }
        constexpr int BV = (BK * BN) / (4 * 256);
#pragma unroll
        for (int v0 = 0; v0 < BV; v0++) {
            int v  = tid + v0 * 256;
            int r  = v / (BN / 4);
            int c4 = (v % (BN / 4)) * 4;
            int kg = kt + r;
            float4 t;
            if constexpr (MODE == M_EZ) {
                int w = c4 >> 6, nc = c4 & 63;
                const float* W = (w == 0) ? W0 : W1;
                t = *(const float4*)&W[(size_t)kg * 64 + nc];
            } else {
                t = *(const float4*)&W0[(size_t)kg * 64 + c4];
            }
            *(float4*)&Bs[r][c4] = t;
        }
        __syncthreads();

#pragma unroll
        for (int kk = 0; kk < BK; kk++) {
            float a[TM], bv[TN];
#pragma unroll
            for (int i = 0; i < TM; i += 4) {
                float4 t = *(const float4*)&As[kk][trow * TM + i];
                a[i] = t.x; a[i + 1] = t.y; a[i + 2] = t.z; a[i + 3] = t.w;
            }
#pragma unroll
            for (int j = 0; j < TN; j += 4) {
                float4 t = *(const float4*)&Bs[kk][tcol * TN + j];
                bv[j] = t.x; bv[j + 1] = t.y; bv[j + 2] = t.z; bv[j + 3] = t.w;
            }
#pragma unroll
            for (int i = 0; i < TM; i++)
#pragma unroll
                for (int j = 0; j < TN; j++)
                    acc[i][j] = fmaf(a[i], bv[j], acc[i][j]);
        }
        __syncthreads();
    }

#pragma unroll
    for (int i = 0; i < TM; i++) {
        int rg = m0 + trow * TM + i;
#pragma unroll
        for (int j = 0; j < TN; j += 4) {
            int ng = tcol * TN + j;
            float4 o;
            if constexpr (MODE == M_EZ) {
                const float* bp = (ng < 64) ? (b0 + ng) : (b1 + (ng - 64));
                float4 bq = *(const float4*)bp;
                o.x = acc[i][j + 0] + bq.x; o.y = acc[i][j + 1] + bq.y;
                o.z = acc[i][j + 2] + bq.z; o.w = acc[i][j + 3] + bq.w;
                *(float4*)&g_c0ez[(size_t)rg * 128 + ng] = o;
            } else {
                float4 bq = *(const float4*)&b0[ng];
                o.x = acc[i][j + 0] + bq.x; o.y = acc[i][j + 1] + bq.y;
                o.z = acc[i][j + 2] + bq.z; o.w = acc[i][j + 3] + bq.w;
                *(float4*)&g_ztwza[(size_t)rg * 64 + ng] = o;
            }
        }
    }
}

// ---------------- write_weight: softmax(control_key @ memory_key^T) ----------------
__global__ void __launch_bounds__(256) ww_k(const float* __restrict__ ck,
                                            const float* __restrict__ mk)
{
    int g = threadIdx.x >> 6;
    int t = threadIdx.x & 63;
    int b = blockIdx.x * 4 + g;
    __shared__ float sck[4][64];
    __shared__ float pmax[4][2];
    __shared__ float psum[4][2];

    sck[g][t] = ck[b * 64 + t];
    __syncthreads();
    float dot = 0.f;
#pragma unroll 8
    for (int k = 0; k < 64; k++) dot = fmaf(sck[g][k], mk[t * 64 + k], dot);

    float mx = dot;
#pragma unroll
    for (int o = 16; o > 0; o >>= 1) mx = fmaxf(mx, __shfl_xor_sync(0xffffffffu, mx, o));
    int wl = t >> 5;
    if ((t & 31) == 0) pmax[g][wl] = mx;
    __syncthreads();
    mx = fmaxf(pmax[g][0], pmax[g][1]);

    float e = __expf(dot - mx);
    float s = e;
#pragma unroll
    for (int o = 16; o > 0; o >>= 1) s += __shfl_xor_sync(0xffffffffu, s, o);
    if ((t & 31) == 0) psum[g][wl] = s;
    __syncthreads();
    s = psum[g][0] + psum[g][1];

    g_ww[b * 64 + t] = e / s;
}

// ---------------- zt + erase ----------------
__global__ void __launch_bounds__(256) zt_erase_k()
{
    int i = blockIdx.x * 256 + threadIdx.x;
    int b = i >> 6, j = i & 63;
    float cwe  = g_c0ez[b * 128 + j];
    float cwz  = g_c0ez[b * 128 + 64 + j];
    float semv = g_sig[b * 192 + j];
    float szmv = g_sig[b * 192 + 64 + j];
    g_zt[i]    = sigmoidf_(cwz + szmv);
    g_erase[i] = sigmoidf_(sigmoidf_(cwe) + sigmoidf_(semv));
}

// ---------------- final: out = mempre*(1 - w*erase) + w*add ----------------
__global__ void __launch_bounds__(256) final_k(float* __restrict__ out)
{
    int b = blockIdx.x;
    int t = threadIdx.x;
    __shared__ float sww[64], ser[64], sadd[64];
    if (t < 64) {
        sww[t] = g_ww[b * 64 + t];
        ser[t] = g_erase[b * 64 + t];
        sadd[t] = tanhf(tanhf(g_ztwza[b * 64 + t]) + tanhf(g_sig[b * 192 + 128 + t]));
    }
    __syncthreads();
    const float4* mp = (const float4*)&g_mempre[(size_t)b * 4096];
    float4* op = (float4*)(out + (size_t)b * 4096);
#pragma unroll
    for (int it = 0; it < 4; it++) {
        int v  = t + it * 256;
        int m  = v >> 4;
        int dv = (v & 15) << 2;
        float w = sww[m];
        float4 x = mp[v];
        float4 r;
        r.x = x.x * (1.f - w * ser[dv + 0]) + w * sadd[dv + 0];
        r.y = x.y * (1.f - w * ser[dv + 1]) + w * sadd[dv + 1];
        r.z = x.z * (1.f - w * ser[dv + 2]) + w * sadd[dv + 2];
        r.w = x.w * (1.f - w * ser[dv + 3]) + w * sadd[dv + 3];
        op[v] = r;
    }
}

// ====================== launch ======================
extern "C" void kernel_launch(void* const* d_in, const int* in_sizes, int n_in,
                              void* d_out, int out_size)
{
    const float* control_key  = (const float*)d_in[0];
    const float* control_qa   = (const float*)d_in[1];
    const float* memory_key   = (const float*)d_in[2];
    const float* memory_value = (const float*)d_in[3];
    const float* We   = (const float*)d_in[4];
    const float* be   = (const float*)d_in[5];
    const float* Wemv = (const float*)d_in[6];
    const float* bemv = (const float*)d_in[7];
    const float* Wza  = (const float*)d_in[8];
    const float* bza  = (const float*)d_in[9];
    const float* Wamv = (const float*)d_in[10];
    const float* bamv = (const float*)d_in[11];
    const float* Wc0  = (const float*)d_in[12];
    const float* bc0  = (const float*)d_in[13];
    const float* Wm1  = (const float*)d_in[14];
    const float* bm1  = (const float*)d_in[15];
    const float* Wz   = (const float*)d_in[16];
    const float* bz   = (const float*)d_in[17];
    const float* Wzmv = (const float*)d_in[18];
    const float* bzmv = (const float*)d_in[19];
    float* out = (float*)d_out;

    constexpr int SM_C0   = 2 * (16384 + 128 * 32 * 4);   // 65536
    constexpr int SM_GATE = 2 * (16384 + 128 * 32 * 4);   // 65536
    constexpr int SM_SIG  = 2 * (16384 + 192 * 32 * 4);   // 81920

    cudaFuncSetAttribute(mma_k<MM_C0, 128, 4096, 4096>,
                         cudaFuncAttributeMaxDynamicSharedMemorySize, SM_C0);
    cudaFuncSetAttribute(mma_k<MM_GATE, 128, 128, 128>,
                         cudaFuncAttributeMaxDynamicSharedMemorySize, SM_GATE);
    cudaFuncSetAttribute(mma_k<MM_SIG, 192, 4096, 4096>,
                         cudaFuncAttributeMaxDynamicSharedMemorySize, SM_SIG);

    // write weights (independent)
    ww_k<<<BB / 4, 256>>>(control_key, memory_key);

    // content0 = qa * sigmoid(memory_value @ Wc0 + bc0)   [B x 128]
    mma_k<MM_C0, 128, 4096, 4096><<<dim3(128, 1), 256, SM_C0>>>(
        memory_value, Wc0, nullptr, nullptr, bc0, nullptr, nullptr, control_qa);

    // c0ez = [c0@We + be | c0@Wz + bz]                    [B x 128]
    gemm_k<M_EZ, 128, 8, 128, 128><<<dim3(BB / 128, 1), 256>>>(We, Wz, be, bz);

    // mempre = memory_value * sigmoid(c0 @ Wm1 + bm1)     [B x 4096]
    mma_k<MM_GATE, 128, 128, 128><<<dim3(128, 32), 256, SM_GATE>>>(
        nullptr, Wm1, nullptr, nullptr, bm1, nullptr, nullptr, memory_value);

    // sig = mempre @ [Wemv|Wzmv|Wamv] + biases            [B x 192]
    mma_k<MM_SIG, 192, 4096, 4096><<<dim3(128, 1), 256, SM_SIG>>>(
        nullptr, Wemv, Wzmv, Wamv, bemv, bzmv, bamv, nullptr);

    // zt, erase
    zt_erase_k<<<BB * 64 / 256, 256>>>();

    // ztwza = zt @ Wza + bza                               [B x 64]
    gemm_k<M_ZA, 64, 4, 64, 64><<<dim3(BB / 128, 1), 256>>>(Wza, nullptr, bza, nullptr);

    // final elementwise
    final_k<<<BB, 256>>>(out);
}